// round 15
// baseline (speedup 1.0000x reference)
#include <cuda_runtime.h>
#include <cuda_bf16.h>
#include <cuda_fp16.h>
#include <math.h>
#include <stdint.h>

#define Bb 8
#define Cc 256
#define Nn 2304
#define BM 64
#define TN 64             // keys per tile
#define NT (Nn / TN)      // 36 tiles, split even/odd between groups

// ---------------- global scratch ----------------
__device__ __align__(16) unsigned short g_Qh[(size_t)Bb * Nn * Cc];   // bf16 hi
__device__ __align__(16) unsigned short g_Ql[(size_t)Bb * Nn * Cc];   // bf16 lo
__device__ __align__(16) unsigned short g_Kh[(size_t)Bb * Nn * Cc];   // bf16 hi
__device__ __align__(16) unsigned short g_Kl[(size_t)Bb * Nn * Cc];   // bf16 lo
__device__ __align__(16) unsigned short g_Vt[(size_t)Bb * Cc * Nn];   // fp16, channel-major

// ---------------- helpers ----------------
__device__ __forceinline__ uint32_t smem_u32(const void* p) {
    uint32_t a;
    asm("{ .reg .u64 t; cvta.to.shared.u64 t, %1; cvt.u32.u64 %0, t; }" : "=r"(a) : "l"(p));
    return a;
}

#define LDSM4(r, addr) \
    asm volatile("ldmatrix.sync.aligned.m8n8.x4.shared.b16 {%0,%1,%2,%3}, [%4];" \
        : "=r"((r)[0]), "=r"((r)[1]), "=r"((r)[2]), "=r"((r)[3]) : "r"(addr))
#define LDSM4T(r, addr) \
    asm volatile("ldmatrix.sync.aligned.m8n8.x4.trans.shared.b16 {%0,%1,%2,%3}, [%4];" \
        : "=r"((r)[0]), "=r"((r)[1]), "=r"((r)[2]), "=r"((r)[3]) : "r"(addr))

#define GBAR(id) asm volatile("bar.sync %0, 128;" :: "r"(id) : "memory")

__device__ __forceinline__ void mma_bf16(float* c, const uint32_t* a,
                                         uint32_t b0, uint32_t b1) {
    asm volatile(
        "mma.sync.aligned.m16n8k16.row.col.f32.bf16.bf16.f32 "
        "{%0,%1,%2,%3}, {%4,%5,%6,%7}, {%8,%9}, {%0,%1,%2,%3};"
        : "+f"(c[0]), "+f"(c[1]), "+f"(c[2]), "+f"(c[3])
        : "r"(a[0]), "r"(a[1]), "r"(a[2]), "r"(a[3]), "r"(b0), "r"(b1));
}

__device__ __forceinline__ void mma_fp16(float* c, const uint32_t* a,
                                         uint32_t b0, uint32_t b1) {
    asm volatile(
        "mma.sync.aligned.m16n8k16.row.col.f32.f16.f16.f32 "
        "{%0,%1,%2,%3}, {%4,%5,%6,%7}, {%8,%9}, {%0,%1,%2,%3};"
        : "+f"(c[0]), "+f"(c[1]), "+f"(c[2]), "+f"(c[3])
        : "r"(a[0]), "r"(a[1]), "r"(a[2]), "r"(a[3]), "r"(b0), "r"(b1));
}

__device__ __forceinline__ void cp16(uint32_t s, const void* g) {
    asm volatile("cp.async.cg.shared.global [%0], [%1], 16;" :: "r"(s), "l"(g) : "memory");
}
#define CP_COMMIT() asm volatile("cp.async.commit_group;" ::: "memory")
#define CP_WAIT2()  asm volatile("cp.async.wait_group 2;" ::: "memory")

__device__ __forceinline__ void split2(float v, unsigned short& h, unsigned short& l) {
    __nv_bfloat16 bh = __float2bfloat16(v);
    float r = v - __bfloat162float(bh);
    h = __bfloat16_as_ushort(bh);
    l = __bfloat16_as_ushort(__float2bfloat16(r));
}

__device__ __forceinline__ void split_pack(float a, float b, uint32_t& h, uint32_t& l) {
    unsigned short ah, al, bh, bl;
    split2(a, ah, al);
    split2(b, bh, bl);
    h = (uint32_t)ah | ((uint32_t)bh << 16);
    l = (uint32_t)al | ((uint32_t)bl << 16);
}

__device__ __forceinline__ uint32_t pack_h2(float a, float b) {
    __half2 h = __floats2half2_rn(a, b);
    return *(uint32_t*)&h;
}

// ---------------------------------------------------------------------------
// HMMA projections (bf16x3), fused fp32->bf16 split on load.
// 64tok x 64co per CTA, 128 threads (4 warps), register-double-buffered
// ck loop over static 36.8KB smem (XH 0, XL 9216, WH 18432, WL 27648;
// pitch 144 bytes).  blockIdx.z = which*8 + b; which: 0=Q(x),1=K(y),2=V(y).
// ---------------------------------------------------------------------------
__global__ __launch_bounds__(128) void proj_hmma(
    const float* __restrict__ x, const float* __restrict__ y,
    const float* __restrict__ Wq, const float* __restrict__ bq,
    const float* __restrict__ Wk, const float* __restrict__ bk,
    const float* __restrict__ Wv, const float* __restrict__ bv)
{
    __shared__ char psm[36864];
    const uint32_t sb = smem_u32(psm);

    const int tid  = threadIdx.x;
    const int wid  = tid >> 5;
    const int lane = tid & 31;
    const int n0    = blockIdx.x * 64;
    const int co0   = blockIdx.y * 64;
    const int which = blockIdx.z >> 3;
    const int b     = blockIdx.z & 7;

    const float* X = (which == 0) ? x : y;
    const float* W = (which == 0) ? Wq : ((which == 1) ? Wk : Wv);
    const float* bias = (which == 0) ? bq : ((which == 1) ? bk : bv);

    const int a_ci = (lane & 7) + ((lane >> 4) & 1) * 8;
    const int a_m  = wid * 16 + ((lane >> 3) & 1) * 8;
    const int b_row = (lane & 7) + (lane >> 4) * 8;
    const int b_k   = ((lane >> 3) & 1) * 8;

    // per-thread staging: 8 float4 of X + 8 float4 of W (chunk 64x64 each)
    float4 xv[8], wv[8];

    auto load_ck = [&](int ck) {
#pragma unroll
        for (int t = 0; t < 8; ++t) {
            int f = tid + t * 128;
            int r = f >> 4, c4 = f & 15;
            xv[t] = *(const float4*)&X[((size_t)b * Cc + ck * 64 + r) * Nn + n0 + c4 * 4];
            wv[t] = *(const float4*)&W[(size_t)(co0 + r) * Cc + ck * 64 + c4 * 4];
        }
    };

    auto sts_ck = [&]() {
#pragma unroll
        for (int t = 0; t < 8; ++t) {
            int f = tid + t * 128;
            int r = f >> 4, c4 = f & 15;
            uint32_t off = (uint32_t)(r * 144 + c4 * 8);
            uint2 h, l;
            split_pack(xv[t].x, xv[t].y, h.x, l.x);
            split_pack(xv[t].z, xv[t].w, h.y, l.y);
            *(uint2*)(psm + off) = h;
            *(uint2*)(psm + 9216 + off) = l;
            split_pack(wv[t].x, wv[t].y, h.x, l.x);
            split_pack(wv[t].z, wv[t].w, h.y, l.y);
            *(uint2*)(psm + 18432 + off) = h;
            *(uint2*)(psm + 27648 + off) = l;
        }
    };

    float acc[8][4];
#pragma unroll
    for (int j = 0; j < 8; j++)
#pragma unroll
        for (int e = 0; e < 4; e++) acc[j][e] = 0.f;

    load_ck(0);

    for (int ck = 0; ck < 4; ++ck) {
        if (ck > 0) __syncthreads();     // prior compute done before overwrite
        sts_ck();
        __syncthreads();
        if (ck + 1 < 4) load_ck(ck + 1); // LDG in flight under compute

#pragma unroll
        for (int ks = 0; ks < 4; ++ks) {
            uint32_t ah[4], al4[4];
            uint32_t aa = (uint32_t)((ks * 16 + a_ci) * 144 + a_m * 2);
            LDSM4T(ah, sb + aa);
            LDSM4T(al4, sb + 9216 + aa);
            uint32_t BH[4][4], BL[4][4];
#pragma unroll
            for (int nb = 0; nb < 4; ++nb) {
                uint32_t ba = (uint32_t)((nb * 16 + b_row) * 144 + (ks * 16 + b_k) * 2);
                LDSM4(BH[nb], sb + 18432 + ba);
                LDSM4(BL[nb], sb + 27648 + ba);
            }
#pragma unroll
            for (int nb = 0; nb < 4; ++nb) {
                mma_bf16(acc[2 * nb],     ah, BH[nb][0], BH[nb][1]);
                mma_bf16(acc[2 * nb + 1], ah, BH[nb][2], BH[nb][3]);
            }
#pragma unroll
            for (int nb = 0; nb < 4; ++nb) {
                mma_bf16(acc[2 * nb],     al4, BH[nb][0], BH[nb][1]);
                mma_bf16(acc[2 * nb + 1], al4, BH[nb][2], BH[nb][3]);
            }
#pragma unroll
            for (int nb = 0; nb < 4; ++nb) {
                mma_bf16(acc[2 * nb],     ah, BL[nb][0], BL[nb][1]);
                mma_bf16(acc[2 * nb + 1], ah, BL[nb][2], BL[nb][3]);
            }
        }
    }

    const int m1 = wid * 16 + (lane >> 2);

    if (which < 2) {
        unsigned short* Gh = which ? g_Kh : g_Qh;
        unsigned short* Gl = which ? g_Kl : g_Ql;
#pragma unroll
        for (int j = 0; j < 8; ++j) {
            int co = j * 8 + (lane & 3) * 2;
            float b0 = bias[co0 + co], b1 = bias[co0 + co + 1];
            uint32_t h01, l01, h23, l23;
            split_pack(acc[j][0] + b0, acc[j][1] + b1, h01, l01);
            split_pack(acc[j][2] + b0, acc[j][3] + b1, h23, l23);
            size_t e1 = ((size_t)b * Nn + n0 + m1) * Cc + co0 + co;
            size_t e2 = e1 + 8 * (size_t)Cc;
            *(uint32_t*)(Gh + e1) = h01;
            *(uint32_t*)(Gl + e1) = l01;
            *(uint32_t*)(Gh + e2) = h23;
            *(uint32_t*)(Gl + e2) = l23;
        }
    } else {
        __syncthreads();                // compute done before smem reuse
        float* stage = (float*)psm;     // [co 64][m 68]
#pragma unroll
        for (int j = 0; j < 8; ++j) {
            int co = j * 8 + (lane & 3) * 2;
            float b0 = bias[co0 + co], b1 = bias[co0 + co + 1];
            stage[co * 68 + m1]           = acc[j][0] + b0;
            stage[(co + 1) * 68 + m1]     = acc[j][1] + b1;
            stage[co * 68 + m1 + 8]       = acc[j][2] + b0;
            stage[(co + 1) * 68 + m1 + 8] = acc[j][3] + b1;
        }
        __syncthreads();
#pragma unroll
        for (int l = tid; l < 2048; l += 128) {
            int co = l >> 5, mp = (l & 31) * 2;
            float v0 = stage[co * 68 + mp], v1 = stage[co * 68 + mp + 1];
            size_t e = ((size_t)b * Cc + co0 + co) * Nn + n0 + mp;
            *(uint32_t*)(g_Vt + e) = pack_h2(v0, v1);
        }
    }
}

// ---------------------------------------------------------------------------
// HMMA flash attention (R13 core, unchanged): two independent 128-thread
// groups, 4-deep cp.async pipeline, guarded O-rescale. bf16x3 S, fp16x1 PV.
// ---------------------------------------------------------------------------
#define SM_QH  256
#define SM_QL  (SM_QH + 33792)            // 34048
#define SM_BUF (SM_QL + 33792)            // 67840: 8 x 18432 (grp x slot)
#define SM_STATS (SM_BUF + 8 * 18432)     // 215296
#define ATTN_SMEM (SM_STATS + 1664)       // 216960

__global__ __launch_bounds__(256, 1) void attn_kernel(float* __restrict__ out)
{
    extern __shared__ char smem[];
    const uint32_t sbase = smem_u32(smem);

    const int tid  = threadIdx.x;
    const int wid  = tid >> 5;
    const int lane = tid & 31;
    const int ltid = tid & 127;
    const int grp  = tid >> 7;
    const int b    = blockIdx.y;
    const int m0   = blockIdx.x * BM;

    const int wm = (wid & 3) * 16;

    const int arow   = wm + (lane & 7) + ((lane >> 3) & 1) * 8;
    const int ak     = (lane >> 4) * 8;
    const int bn_row = (lane & 7) + (lane >> 4) * 8;
    const int bk_add = ((lane >> 3) & 1) * 8;

    const uint32_t qbH = sbase + SM_QH, qbL = sbase + SM_QL;

    auto buf_base = [&](int slot) -> uint32_t {
        return sbase + SM_BUF + (uint32_t)(grp * 4 + slot) * 18432u;
    };

    auto issue_chunk = [&](int ci) {
        int t = grp + (ci >> 3) * 2, j = ci & 7;
        int n0 = t * TN;
        uint32_t base = buf_base(ci & 3);
        if (j < 4) {
            const char* Gh = (const char*)g_Kh;
            const char* Gl = (const char*)g_Kl;
#pragma unroll
            for (int tt = 0; tt < 4; ++tt) {
                int l = ltid + tt * 128;
                int n = l >> 3, c8 = l & 7;
                size_t gb = (((size_t)b * Nn + n0 + n) * Cc + j * 64 + c8 * 8) * 2;
                uint32_t so = (uint32_t)((n * 72 + c8 * 8) * 2);
                cp16(base + so, Gh + gb);
                cp16(base + 9216 + so, Gl + gb);
            }
        } else {
            int vc = j - 4;
            const char* Gv = (const char*)g_Vt;
#pragma unroll
            for (int tt = 0; tt < 4; ++tt) {
                int l = ltid + tt * 128;
                int c = l >> 3, k8 = l & 7;
                size_t gb = (((size_t)b * Cc + vc * 64 + c) * Nn + n0 + k8 * 8) * 2;
                uint32_t so = (uint32_t)((c * 72 + k8 * 8) * 2);
                cp16(base + so, Gv + gb);
            }
        }
    };

    issue_chunk(0); CP_COMMIT();
    issue_chunk(1); CP_COMMIT();

    {
        const uint4* Gh = (const uint4*)g_Qh;
        const uint4* Gl = (const uint4*)g_Ql;
        uint4* Dh = (uint4*)(smem + SM_QH);
        uint4* Dl = (uint4*)(smem + SM_QL);
#pragma unroll
        for (int l = tid; l < 2048; l += 256) {
            int m = l >> 5, c8 = l & 31;
            size_t gi = (((size_t)b * Nn + m0 + m) * Cc + c8 * 8) >> 3;
            int d = m * 33 + c8;
            Dh[d] = Gh[gi];
            Dl[d] = Gl[gi];
        }
    }
    issue_chunk(2); CP_COMMIT();
    __syncthreads();

    float oacc[32][4];
#pragma unroll
    for (int f = 0; f < 32; f++)
#pragma unroll
        for (int e = 0; e < 4; e++) oacc[f][e] = 0.f;

    float sacc[8][4];
    uint32_t pF01[8], pF23[8];
    float s0 = 0.f, s1 = 0.f;
    float m_a = -1e30f, m_b = -1e30f;

    const int NCH = (NT / 2) * 8;
    const int bar_id = grp + 1;

    for (int ci = 0; ci < NCH; ++ci) {
        const int j = ci & 7;
        CP_WAIT2();
        GBAR(bar_id);
        if (ci + 3 < NCH) issue_chunk(ci + 3);
        CP_COMMIT();

        const uint32_t bB = buf_base(ci & 3);

        if (j < 4) {
            const int cc = j;
            if (j == 0) {
#pragma unroll
                for (int f = 0; f < 8; f++)
#pragma unroll
                    for (int e = 0; e < 4; e++) sacc[f][e] = 0.f;
            }
#pragma unroll
            for (int ks = 0; ks < 4; ++ks) {
                const int k0 = ks * 16;
                uint32_t qh[4], ql[4];
                uint32_t qa = (uint32_t)((arow * 264 + cc * 64 + k0 + ak) * 2);
                LDSM4(qh, qbH + qa);
                LDSM4(ql, qbL + qa);
                uint32_t BH[4][4], BL[4][4];
#pragma unroll
                for (int nb = 0; nb < 4; ++nb) {
                    uint32_t kaddr = (uint32_t)(((nb * 16 + bn_row) * 72 + k0 + bk_add) * 2);
                    LDSM4(BH[nb], bB + kaddr);
                    LDSM4(BL[nb], bB + 9216 + kaddr);
                }
#pragma unroll
                for (int nb = 0; nb < 4; ++nb) {
                    mma_bf16(sacc[2 * nb],     qh, BH[nb][0], BH[nb][1]);
                    mma_bf16(sacc[2 * nb + 1], qh, BH[nb][2], BH[nb][3]);
                }
#pragma unroll
                for (int nb = 0; nb < 4; ++nb) {
                    mma_bf16(sacc[2 * nb],     ql, BH[nb][0], BH[nb][1]);
                    mma_bf16(sacc[2 * nb + 1], ql, BH[nb][2], BH[nb][3]);
                }
#pragma unroll
                for (int nb = 0; nb < 4; ++nb) {
                    mma_bf16(sacc[2 * nb],     qh, BL[nb][0], BL[nb][1]);
                    mma_bf16(sacc[2 * nb + 1], qh, BL[nb][2], BL[nb][3]);
                }
            }
            if (j == 3) {
                float ma = -1e30f, mb = -1e30f;
#pragma unroll
                for (int f = 0; f < 8; ++f) {
                    ma = fmaxf(ma, fmaxf(sacc[f][0], sacc[f][1]));
                    mb = fmaxf(mb, fmaxf(sacc[f][2], sacc[f][3]));
                }
                ma = fmaxf(ma, __shfl_xor_sync(0xffffffffu, ma, 1));
                ma = fmaxf(ma, __shfl_xor_sync(0xffffffffu, ma, 2));
                mb = fmaxf(mb, __shfl_xor_sync(0xffffffffu, mb, 1));
                mb = fmaxf(mb, __shfl_xor_sync(0xffffffffu, mb, 2));
                float mna = fmaxf(m_a, ma), mnb = fmaxf(m_b, mb);
                float aa = __expf(m_a - mna), ab = __expf(m_b - mnb);
                m_a = mna; m_b = mnb;
                s0 *= aa; s1 *= ab;
#pragma unroll
                for (int f = 0; f < 8; ++f) {
                    float p0 = __expf(sacc[f][0] - m_a);
                    float p1 = __expf(sacc[f][1] - m_a);
                    float p2 = __expf(sacc[f][2] - m_b);
                    float p3 = __expf(sacc[f][3] - m_b);
                    s0 += p0 + p1;
                    s1 += p2 + p3;
                    pF01[f] = pack_h2(p0, p1);
                    pF23[f] = pack_h2(p2, p3);
                }
                if (aa < 1.f || ab < 1.f) {
#pragma unroll
                    for (int f = 0; f < 32; ++f) {
                        oacc[f][0] *= aa; oacc[f][1] *= aa;
                        oacc[f][2] *= ab; oacc[f][3] *= ab;
                    }
                }
            }
        } else {
            const int vc = j - 4;
#pragma unroll
            for (int ks = 0; ks < 4; ++ks) {
                const int k0 = ks * 16;
                uint32_t paf[4] = {pF01[2 * ks], pF23[2 * ks],
                                   pF01[2 * ks + 1], pF23[2 * ks + 1]};
#pragma unroll
                for (int g2 = 0; g2 < 2; ++g2) {
                    uint32_t VH0[4], VH1[4];
                    uint32_t va0 = (uint32_t)((((2 * g2) * 16 + bn_row) * 72 + k0 + bk_add) * 2);
                    uint32_t va1 = (uint32_t)((((2 * g2 + 1) * 16 + bn_row) * 72 + k0 + bk_add) * 2);
                    LDSM4(VH0, bB + va0);
                    LDSM4(VH1, bB + va1);
                    mma_fp16(oacc[vc * 8 + g2 * 4],     paf, VH0[0], VH0[1]);
                    mma_fp16(oacc[vc * 8 + g2 * 4 + 1], paf, VH0[2], VH0[3]);
                    mma_fp16(oacc[vc * 8 + g2 * 4 + 2], paf, VH1[0], VH1[1]);
                    mma_fp16(oacc[vc * 8 + g2 * 4 + 3], paf, VH1[2], VH1[3]);
                }
            }
        }
    }

    // ================ epilogue: merge groups with max factors ============
    __syncthreads();
    s0 += __shfl_xor_sync(0xffffffffu, s0, 1);
    s0 += __shfl_xor_sync(0xffffffffu, s0, 2);
    s1 += __shfl_xor_sync(0xffffffffu, s1, 1);
    s1 += __shfl_xor_sync(0xffffffffu, s1, 2);

    float* m_sm  = (float*)(smem + SM_STATS);        // [128]
    float* rs_sm = m_sm + 128;                       // [128]
    float* g0_sm = rs_sm + 128;                      // [64]
    float* g1_sm = g0_sm + 64;                       // [64]
    const int r = wm + (lane >> 2);
    if ((lane & 3) == 0) {
        m_sm[grp * 64 + r]      = m_a;
        rs_sm[grp * 64 + r]     = s0;
        m_sm[grp * 64 + r + 8]  = m_b;
        rs_sm[grp * 64 + r + 8] = s1;
    }
    __syncthreads();
    if (tid < 64) {
        float m0v = m_sm[tid], m1v = m_sm[64 + tid];
        float r0 = rs_sm[tid], r1 = rs_sm[64 + tid];
        float REF = fmaxf(m0v, m1v);
        float f0 = __expf(m0v - REF), f1 = __expf(m1v - REF);
        float inv = 1.f / (f0 * r0 + f1 * r1);
        g0_sm[tid] = f0 * inv;
        g1_sm[tid] = f1 * inv;
    }
    __syncthreads();

    float* st1 = (float*)(smem + SM_QH);     // [64 rows][pitch 260]
    if (grp == 1) {
        float ga = g1_sm[r], gb = g1_sm[r + 8];
#pragma unroll
        for (int q = 0; q < 32; ++q) {
            int ch = q * 8 + (lane & 3) * 2;
            st1[r * 260 + ch]           = oacc[q][0] * ga;
            st1[r * 260 + ch + 1]       = oacc[q][1] * ga;
            st1[(r + 8) * 260 + ch]     = oacc[q][2] * gb;
            st1[(r + 8) * 260 + ch + 1] = oacc[q][3] * gb;
        }
    }
    __syncthreads();
    float* st2 = (float*)(smem + SM_BUF);    // [256 ch][pitch 68]
    if (grp == 0) {
        float ga = g0_sm[r], gb = g0_sm[r + 8];
#pragma unroll
        for (int q = 0; q < 32; ++q) {
            int ch = q * 8 + (lane & 3) * 2;
            st2[ch * 68 + r]           = oacc[q][0] * ga + st1[r * 260 + ch];
            st2[(ch + 1) * 68 + r]     = oacc[q][1] * ga + st1[r * 260 + ch + 1];
            st2[ch * 68 + r + 8]       = oacc[q][2] * gb + st1[(r + 8) * 260 + ch];
            st2[(ch + 1) * 68 + r + 8] = oacc[q][3] * gb + st1[(r + 8) * 260 + ch + 1];
        }
    }
    __syncthreads();
    float* outb = out + (size_t)b * Cc * Nn;
#pragma unroll
    for (int l = tid; l < 16384; l += 256) {
        int ch = l >> 6, m = l & 63;
        outb[(size_t)ch * Nn + m0 + m] = st2[ch * 68 + m];
    }
}

// ---------------------------------------------------------------------------
extern "C" void kernel_launch(void* const* d_in, const int* in_sizes, int n_in,
                              void* d_out, int out_size)
{
    (void)in_sizes; (void)n_in; (void)out_size;
    const float* x  = (const float*)d_in[0];
    const float* y  = (const float*)d_in[1];
    const float* Wq = (const float*)d_in[2];
    const float* bq = (const float*)d_in[3];
    const float* Wk = (const float*)d_in[4];
    const float* bk = (const float*)d_in[5];
    const float* Wv = (const float*)d_in[6];
    const float* bv = (const float*)d_in[7];
    float* out = (float*)d_out;

    proj_hmma<<<dim3(Nn / 64, Cc / 64, 24), 128>>>(x, y, Wq, bq, Wk, bk, Wv, bv);

    cudaFuncSetAttribute(attn_kernel,
                         cudaFuncAttributeMaxDynamicSharedMemorySize, ATTN_SMEM);
    dim3 ag(Nn / BM, Bb);
    attn_kernel<<<ag, 256, ATTN_SMEM>>>(out);
}

// round 17
// speedup vs baseline: 1.0144x; 1.0144x over previous
#include <cuda_runtime.h>
#include <cuda_bf16.h>
#include <cuda_fp16.h>
#include <math.h>
#include <stdint.h>

#define Bb 8
#define Cc 256
#define Nn 2304
#define BM 64
#define TN 64             // keys per tile
#define NT (Nn / TN)      // 36 tiles, split even/odd between groups

// ---------------- global scratch ----------------
__device__ __align__(16) unsigned short g_Qh[(size_t)Bb * Nn * Cc];   // bf16 hi
__device__ __align__(16) unsigned short g_Ql[(size_t)Bb * Nn * Cc];   // bf16 lo
__device__ __align__(16) unsigned short g_Kh[(size_t)Bb * Nn * Cc];   // bf16 hi
__device__ __align__(16) unsigned short g_Kl[(size_t)Bb * Nn * Cc];   // bf16 lo
__device__ __align__(16) unsigned short g_Vt[(size_t)Bb * Cc * Nn];   // fp16, channel-major
// inputs split to bf16 hi/lo (channel-major, same layout as x/y)
__device__ __align__(16) unsigned short g_Xh[(size_t)Bb * Cc * Nn];
__device__ __align__(16) unsigned short g_Xl[(size_t)Bb * Cc * Nn];
__device__ __align__(16) unsigned short g_Yh[(size_t)Bb * Cc * Nn];
__device__ __align__(16) unsigned short g_Yl[(size_t)Bb * Cc * Nn];
// weights split ([co][ci], row-major)
__device__ __align__(16) unsigned short g_Wh[3][Cc * Cc];
__device__ __align__(16) unsigned short g_Wl[3][Cc * Cc];

// ---------------- helpers ----------------
__device__ __forceinline__ uint32_t smem_u32(const void* p) {
    uint32_t a;
    asm("{ .reg .u64 t; cvta.to.shared.u64 t, %1; cvt.u32.u64 %0, t; }" : "=r"(a) : "l"(p));
    return a;
}

#define LDSM4(r, addr) \
    asm volatile("ldmatrix.sync.aligned.m8n8.x4.shared.b16 {%0,%1,%2,%3}, [%4];" \
        : "=r"((r)[0]), "=r"((r)[1]), "=r"((r)[2]), "=r"((r)[3]) : "r"(addr))
#define LDSM4T(r, addr) \
    asm volatile("ldmatrix.sync.aligned.m8n8.x4.trans.shared.b16 {%0,%1,%2,%3}, [%4];" \
        : "=r"((r)[0]), "=r"((r)[1]), "=r"((r)[2]), "=r"((r)[3]) : "r"(addr))

#define GBAR(id) asm volatile("bar.sync %0, 128;" :: "r"(id) : "memory")

__device__ __forceinline__ void mma_bf16(float* c, const uint32_t* a,
                                         uint32_t b0, uint32_t b1) {
    asm volatile(
        "mma.sync.aligned.m16n8k16.row.col.f32.bf16.bf16.f32 "
        "{%0,%1,%2,%3}, {%4,%5,%6,%7}, {%8,%9}, {%0,%1,%2,%3};"
        : "+f"(c[0]), "+f"(c[1]), "+f"(c[2]), "+f"(c[3])
        : "r"(a[0]), "r"(a[1]), "r"(a[2]), "r"(a[3]), "r"(b0), "r"(b1));
}

__device__ __forceinline__ void mma_fp16(float* c, const uint32_t* a,
                                         uint32_t b0, uint32_t b1) {
    asm volatile(
        "mma.sync.aligned.m16n8k16.row.col.f32.f16.f16.f32 "
        "{%0,%1,%2,%3}, {%4,%5,%6,%7}, {%8,%9}, {%0,%1,%2,%3};"
        : "+f"(c[0]), "+f"(c[1]), "+f"(c[2]), "+f"(c[3])
        : "r"(a[0]), "r"(a[1]), "r"(a[2]), "r"(a[3]), "r"(b0), "r"(b1));
}

__device__ __forceinline__ void cp16(uint32_t s, const void* g) {
    asm volatile("cp.async.cg.shared.global [%0], [%1], 16;" :: "r"(s), "l"(g) : "memory");
}
#define CP_COMMIT() asm volatile("cp.async.commit_group;" ::: "memory")
#define CP_WAIT1()  asm volatile("cp.async.wait_group 1;" ::: "memory")
#define CP_WAIT2()  asm volatile("cp.async.wait_group 2;" ::: "memory")

__device__ __forceinline__ void split2(float v, unsigned short& h, unsigned short& l) {
    __nv_bfloat16 bh = __float2bfloat16(v);
    float r = v - __bfloat162float(bh);
    h = __bfloat16_as_ushort(bh);
    l = __bfloat16_as_ushort(__float2bfloat16(r));
}

__device__ __forceinline__ void split_pack(float a, float b, uint32_t& h, uint32_t& l) {
    unsigned short ah, al, bh, bl;
    split2(a, ah, al);
    split2(b, bh, bl);
    h = (uint32_t)ah | ((uint32_t)bh << 16);
    l = (uint32_t)al | ((uint32_t)bl << 16);
}

__device__ __forceinline__ uint32_t pack_h2(float a, float b) {
    __half2 h = __floats2half2_rn(a, b);
    return *(uint32_t*)&h;
}

// ---------------------------------------------------------------------------
// Prep: split x,y (fp32) -> bf16 hi/lo. grid (2304,1,2) x 256
// ---------------------------------------------------------------------------
__global__ __launch_bounds__(256) void prep_xy(const float4* __restrict__ x,
                                               const float4* __restrict__ y)
{
    const int z = blockIdx.z;
    const float4* src = z ? y : x;
    uint4* H = (uint4*)(z ? g_Yh : g_Xh);
    uint4* L = (uint4*)(z ? g_Yl : g_Xl);
    size_t i = (size_t)blockIdx.x * 512 + threadIdx.x * 2;
    float4 f0 = src[i], f1 = src[i + 1];
    uint4 h, l;
    split_pack(f0.x, f0.y, h.x, l.x);
    split_pack(f0.z, f0.w, h.y, l.y);
    split_pack(f1.x, f1.y, h.z, l.z);
    split_pack(f1.z, f1.w, h.w, l.w);
    H[i >> 1] = h;
    L[i >> 1] = l;
}

// Prep: split Wq/Wk/Wv. grid (64,1,3) x 256
__global__ __launch_bounds__(256) void prep_w(const float4* __restrict__ Wq,
                                              const float4* __restrict__ Wk,
                                              const float4* __restrict__ Wv)
{
    const int z = blockIdx.z;
    const float4* src = (z == 0) ? Wq : ((z == 1) ? Wk : Wv);
    uint2* H = (uint2*)g_Wh[z];
    uint2* L = (uint2*)g_Wl[z];
    int i = blockIdx.x * 256 + threadIdx.x;
    float4 f = src[i];
    uint2 h, l;
    split_pack(f.x, f.y, h.x, l.x);
    split_pack(f.z, f.w, h.y, l.y);
    H[i] = h;
    L[i] = l;
}

// ---------------------------------------------------------------------------
// HMMA projections (bf16x3): 64tok x 64co per CTA, 128 threads (4 warps).
// SMALL-CHUNK 3-SLOT cp.async pipeline: chunk = 32 ci; slot 19456 B
// (XH 0 [32ci x 64n, pitch 144B], XL 4608, WH 9216 [64co x 32ci, pitch 80B],
//  WL 14336). 8 chunks, lookahead 2.
// ---------------------------------------------------------------------------
#define PSLOT 19456

__global__ __launch_bounds__(128) void proj_hmma(
    const float* __restrict__ bq, const float* __restrict__ bk,
    const float* __restrict__ bv)
{
    __shared__ __align__(16) char psm[3 * PSLOT];
    const uint32_t sb = smem_u32(psm);

    const int tid  = threadIdx.x;
    const int wid  = tid >> 5;
    const int lane = tid & 31;
    const int n0    = blockIdx.x * 64;
    const int co0   = blockIdx.y * 64;
    const int which = blockIdx.z >> 3;
    const int b     = blockIdx.z & 7;

    const unsigned short* Xh = (which == 0) ? g_Xh : g_Yh;
    const unsigned short* Xl = (which == 0) ? g_Xl : g_Yl;
    const unsigned short* Wh = g_Wh[which];
    const unsigned short* Wl = g_Wl[which];
    const float* bias = (which == 0) ? bq : ((which == 1) ? bk : bv);

    const int a_ci = (lane & 7) + ((lane >> 4) & 1) * 8;
    const int a_m  = wid * 16 + ((lane >> 3) & 1) * 8;
    const int b_row = (lane & 7) + (lane >> 4) * 8;
    const int b_k   = ((lane >> 3) & 1) * 8;

    auto issue_ck = [&](int ck) {
        uint32_t base = sb + (uint32_t)(ck % 3) * PSLOT;
        // X chunk: [32 ci][64 n] hi/lo, pitch 144 B
#pragma unroll
        for (int t = 0; t < 2; ++t) {
            int l = tid + t * 128;
            int r = l >> 3, c8 = l & 7;
            size_t xg = (((size_t)b * Cc + ck * 32 + r) * Nn + n0 + c8 * 8) * 2;
            uint32_t xo = (uint32_t)(r * 144 + c8 * 16);
            cp16(base + xo, (const char*)Xh + xg);
            cp16(base + 4608 + xo, (const char*)Xl + xg);
        }
        // W chunk: [64 co][32 ci] hi/lo, pitch 80 B (16B-aligned rows)
#pragma unroll
        for (int t = 0; t < 2; ++t) {
            int l = tid + t * 128;
            int r = l >> 2, c4 = l & 3;
            size_t wg = (size_t)((co0 + r) * Cc + ck * 32 + c4 * 8) * 2;
            uint32_t wo = (uint32_t)(r * 80 + c4 * 16);
            cp16(base + 9216 + wo, (const char*)Wh + wg);
            cp16(base + 14336 + wo, (const char*)Wl + wg);
        }
    };

    float acc[8][4];
#pragma unroll
    for (int j = 0; j < 8; j++)
#pragma unroll
        for (int e = 0; e < 4; e++) acc[j][e] = 0.f;

    issue_ck(0); CP_COMMIT();
    issue_ck(1); CP_COMMIT();

    for (int ck = 0; ck < 8; ++ck) {
        CP_WAIT1();                      // chunk ck landed (ck+1 in flight)
        __syncthreads();                 // visible; slot ck+2 free
        if (ck + 2 < 8) issue_ck(ck + 2);
        CP_COMMIT();

        uint32_t base = sb + (uint32_t)(ck % 3) * PSLOT;
#pragma unroll
        for (int ks = 0; ks < 2; ++ks) {
            uint32_t ah[4], al4[4];
            uint32_t aa = (uint32_t)((ks * 16 + a_ci) * 144 + a_m * 2);
            LDSM4T(ah, base + aa);
            LDSM4T(al4, base + 4608 + aa);
            uint32_t BH[4][4], BL[4][4];
#pragma unroll
            for (int nb = 0; nb < 4; ++nb) {
                uint32_t ba = (uint32_t)((nb * 16 + b_row) * 80 + (ks * 16 + b_k) * 2);
                LDSM4(BH[nb], base + 9216 + ba);
                LDSM4(BL[nb], base + 14336 + ba);
            }
#pragma unroll
            for (int nb = 0; nb < 4; ++nb) {
                mma_bf16(acc[2 * nb],     ah, BH[nb][0], BH[nb][1]);
                mma_bf16(acc[2 * nb + 1], ah, BH[nb][2], BH[nb][3]);
            }
#pragma unroll
            for (int nb = 0; nb < 4; ++nb) {
                mma_bf16(acc[2 * nb],     al4, BH[nb][0], BH[nb][1]);
                mma_bf16(acc[2 * nb + 1], al4, BH[nb][2], BH[nb][3]);
            }
#pragma unroll
            for (int nb = 0; nb < 4; ++nb) {
                mma_bf16(acc[2 * nb],     ah, BL[nb][0], BL[nb][1]);
                mma_bf16(acc[2 * nb + 1], ah, BL[nb][2], BL[nb][3]);
            }
        }
    }

    const int m1 = wid * 16 + (lane >> 2);

    if (which < 2) {
        unsigned short* Gh = which ? g_Kh : g_Qh;
        unsigned short* Gl = which ? g_Kl : g_Ql;
#pragma unroll
        for (int j = 0; j < 8; ++j) {
            int co = j * 8 + (lane & 3) * 2;
            float b0 = bias[co0 + co], b1 = bias[co0 + co + 1];
            uint32_t h01, l01, h23, l23;
            split_pack(acc[j][0] + b0, acc[j][1] + b1, h01, l01);
            split_pack(acc[j][2] + b0, acc[j][3] + b1, h23, l23);
            size_t e1 = ((size_t)b * Nn + n0 + m1) * Cc + co0 + co;
            size_t e2 = e1 + 8 * (size_t)Cc;
            *(uint32_t*)(Gh + e1) = h01;
            *(uint32_t*)(Gl + e1) = l01;
            *(uint32_t*)(Gh + e2) = h23;
            *(uint32_t*)(Gl + e2) = l23;
        }
    } else {
        __syncthreads();                // compute done before smem reuse
        float* stage = (float*)psm;     // [co 64][m 68] = 17.4 KB
#pragma unroll
        for (int j = 0; j < 8; ++j) {
            int co = j * 8 + (lane & 3) * 2;
            float b0 = bias[co0 + co], b1 = bias[co0 + co + 1];
            stage[co * 68 + m1]           = acc[j][0] + b0;
            stage[(co + 1) * 68 + m1]     = acc[j][1] + b1;
            stage[co * 68 + m1 + 8]       = acc[j][2] + b0;
            stage[(co + 1) * 68 + m1 + 8] = acc[j][3] + b1;
        }
        __syncthreads();
#pragma unroll
        for (int l = tid; l < 2048; l += 128) {
            int co = l >> 5, mp = (l & 31) * 2;
            float v0 = stage[co * 68 + mp], v1 = stage[co * 68 + mp + 1];
            size_t e = ((size_t)b * Cc + co0 + co) * Nn + n0 + mp;
            *(uint32_t*)(g_Vt + e) = pack_h2(v0, v1);
        }
    }
}

// ---------------------------------------------------------------------------
// HMMA flash attention (R13 core, unchanged): two independent 128-thread
// groups, 4-deep cp.async pipeline, guarded O-rescale. bf16x3 S, fp16x1 PV.
// ---------------------------------------------------------------------------
#define SM_QH  256
#define SM_QL  (SM_QH + 33792)            // 34048
#define SM_BUF (SM_QL + 33792)            // 67840: 8 x 18432 (grp x slot)
#define SM_STATS (SM_BUF + 8 * 18432)     // 215296
#define ATTN_SMEM (SM_STATS + 1664)       // 216960

__global__ __launch_bounds__(256, 1) void attn_kernel(float* __restrict__ out)
{
    extern __shared__ char smem[];
    const uint32_t sbase = smem_u32(smem);

    const int tid  = threadIdx.x;
    const int wid  = tid >> 5;
    const int lane = tid & 31;
    const int ltid = tid & 127;
    const int grp  = tid >> 7;
    const int b    = blockIdx.y;
    const int m0   = blockIdx.x * BM;

    const int wm = (wid & 3) * 16;

    const int arow   = wm + (lane & 7) + ((lane >> 3) & 1) * 8;
    const int ak     = (lane >> 4) * 8;
    const int bn_row = (lane & 7) + (lane >> 4) * 8;
    const int bk_add = ((lane >> 3) & 1) * 8;

    const uint32_t qbH = sbase + SM_QH, qbL = sbase + SM_QL;

    auto buf_base = [&](int slot) -> uint32_t {
        return sbase + SM_BUF + (uint32_t)(grp * 4 + slot) * 18432u;
    };

    auto issue_chunk = [&](int ci) {
        int t = grp + (ci >> 3) * 2, j = ci & 7;
        int n0 = t * TN;
        uint32_t base = buf_base(ci & 3);
        if (j < 4) {
            const char* Gh = (const char*)g_Kh;
            const char* Gl = (const char*)g_Kl;
#pragma unroll
            for (int tt = 0; tt < 4; ++tt) {
                int l = ltid + tt * 128;
                int n = l >> 3, c8 = l & 7;
                size_t gb = (((size_t)b * Nn + n0 + n) * Cc + j * 64 + c8 * 8) * 2;
                uint32_t so = (uint32_t)((n * 72 + c8 * 8) * 2);
                cp16(base + so, Gh + gb);
                cp16(base + 9216 + so, Gl + gb);
            }
        } else {
            int vc = j - 4;
            const char* Gv = (const char*)g_Vt;
#pragma unroll
            for (int tt = 0; tt < 4; ++tt) {
                int l = ltid + tt * 128;
                int c = l >> 3, k8 = l & 7;
                size_t gb = (((size_t)b * Cc + vc * 64 + c) * Nn + n0 + k8 * 8) * 2;
                uint32_t so = (uint32_t)((c * 72 + k8 * 8) * 2);
                cp16(base + so, Gv + gb);
            }
        }
    };

    issue_chunk(0); CP_COMMIT();
    issue_chunk(1); CP_COMMIT();

    {
        const uint4* Gh = (const uint4*)g_Qh;
        const uint4* Gl = (const uint4*)g_Ql;
        uint4* Dh = (uint4*)(smem + SM_QH);
        uint4* Dl = (uint4*)(smem + SM_QL);
#pragma unroll
        for (int l = tid; l < 2048; l += 256) {
            int m = l >> 5, c8 = l & 31;
            size_t gi = (((size_t)b * Nn + m0 + m) * Cc + c8 * 8) >> 3;
            int d = m * 33 + c8;
            Dh[d] = Gh[gi];
            Dl[d] = Gl[gi];
        }
    }
    issue_chunk(2); CP_COMMIT();
    __syncthreads();

    float oacc[32][4];
#pragma unroll
    for (int f = 0; f < 32; f++)
#pragma unroll
        for (int e = 0; e < 4; e++) oacc[f][e] = 0.f;

    float sacc[8][4];
    uint32_t pF01[8], pF23[8];
    float s0 = 0.f, s1 = 0.f;
    float m_a = -1e30f, m_b = -1e30f;

    const int NCH = (NT / 2) * 8;
    const int bar_id = grp + 1;

    for (int ci = 0; ci < NCH; ++ci) {
        const int j = ci & 7;
        CP_WAIT2();
        GBAR(bar_id);
        if (ci + 3 < NCH) issue_chunk(ci + 3);
        CP_COMMIT();

        const uint32_t bB = buf_base(ci & 3);

        if (j < 4) {
            const int cc = j;
            if (j == 0) {
#pragma unroll
                for (int f = 0; f < 8; f++)
#pragma unroll
                    for (int e = 0; e < 4; e++) sacc[f][e] = 0.f;
            }
#pragma unroll
            for (int ks = 0; ks < 4; ++ks) {
                const int k0 = ks * 16;
                uint32_t qh[4], ql[4];
                uint32_t qa = (uint32_t)((arow * 264 + cc * 64 + k0 + ak) * 2);
                LDSM4(qh, qbH + qa);
                LDSM4(ql, qbL + qa);
                uint32_t BH[4][4], BL[4][4];
#pragma unroll
                for (int nb = 0; nb < 4; ++nb) {
                    uint32_t kaddr = (uint32_t)(((nb * 16 + bn_row) * 72 + k0 + bk_add) * 2);
                    LDSM4(BH[nb], bB + kaddr);
                    LDSM4(BL[nb], bB + 9216 + kaddr);
                }
#pragma unroll
                for (int nb = 0; nb < 4; ++nb) {
                    mma_bf16(sacc[2 * nb],     qh, BH[nb][0], BH[nb][1]);
                    mma_bf16(sacc[2 * nb + 1], qh, BH[nb][2], BH[nb][3]);
                }
#pragma unroll
                for (int nb = 0; nb < 4; ++nb) {
                    mma_bf16(sacc[2 * nb],     ql, BH[nb][0], BH[nb][1]);
                    mma_bf16(sacc[2 * nb + 1], ql, BH[nb][2], BH[nb][3]);
                }
#pragma unroll
                for (int nb = 0; nb < 4; ++nb) {
                    mma_bf16(sacc[2 * nb],     qh, BL[nb][0], BL[nb][1]);
                    mma_bf16(sacc[2 * nb + 1], qh, BL[nb][2], BL[nb][3]);
                }
            }
            if (j == 3) {
                float ma = -1e30f, mb = -1e30f;
#pragma unroll
                for (int f = 0; f < 8; ++f) {
                    ma = fmaxf(ma, fmaxf(sacc[f][0], sacc[f][1]));
                    mb = fmaxf(mb, fmaxf(sacc[f][2], sacc[f][3]));
                }
                ma = fmaxf(ma, __shfl_xor_sync(0xffffffffu, ma, 1));
                ma = fmaxf(ma, __shfl_xor_sync(0xffffffffu, ma, 2));
                mb = fmaxf(mb, __shfl_xor_sync(0xffffffffu, mb, 1));
                mb = fmaxf(mb, __shfl_xor_sync(0xffffffffu, mb, 2));
                float mna = fmaxf(m_a, ma), mnb = fmaxf(m_b, mb);
                float aa = __expf(m_a - mna), ab = __expf(m_b - mnb);
                m_a = mna; m_b = mnb;
                s0 *= aa; s1 *= ab;
#pragma unroll
                for (int f = 0; f < 8; ++f) {
                    float p0 = __expf(sacc[f][0] - m_a);
                    float p1 = __expf(sacc[f][1] - m_a);
                    float p2 = __expf(sacc[f][2] - m_b);
                    float p3 = __expf(sacc[f][3] - m_b);
                    s0 += p0 + p1;
                    s1 += p2 + p3;
                    pF01[f] = pack_h2(p0, p1);
                    pF23[f] = pack_h2(p2, p3);
                }
                if (aa < 1.f || ab < 1.f) {
#pragma unroll
                    for (int f = 0; f < 32; ++f) {
                        oacc[f][0] *= aa; oacc[f][1] *= aa;
                        oacc[f][2] *= ab; oacc[f][3] *= ab;
                    }
                }
            }
        } else {
            const int vc = j - 4;
#pragma unroll
            for (int ks = 0; ks < 4; ++ks) {
                const int k0 = ks * 16;
                uint32_t paf[4] = {pF01[2 * ks], pF23[2 * ks],
                                   pF01[2 * ks + 1], pF23[2 * ks + 1]};
#pragma unroll
                for (int g2 = 0; g2 < 2; ++g2) {
                    uint32_t VH0[4], VH1[4];
                    uint32_t va0 = (uint32_t)((((2 * g2) * 16 + bn_row) * 72 + k0 + bk_add) * 2);
                    uint32_t va1 = (uint32_t)((((2 * g2 + 1) * 16 + bn_row) * 72 + k0 + bk_add) * 2);
                    LDSM4(VH0, bB + va0);
                    LDSM4(VH1, bB + va1);
                    mma_fp16(oacc[vc * 8 + g2 * 4],     paf, VH0[0], VH0[1]);
                    mma_fp16(oacc[vc * 8 + g2 * 4 + 1], paf, VH0[2], VH0[3]);
                    mma_fp16(oacc[vc * 8 + g2 * 4 + 2], paf, VH1[0], VH1[1]);
                    mma_fp16(oacc[vc * 8 + g2 * 4 + 3], paf, VH1[2], VH1[3]);
                }
            }
        }
    }

    // ================ epilogue: merge groups with max factors ============
    __syncthreads();
    s0 += __shfl_xor_sync(0xffffffffu, s0, 1);
    s0 += __shfl_xor_sync(0xffffffffu, s0, 2);
    s1 += __shfl_xor_sync(0xffffffffu, s1, 1);
    s1 += __shfl_xor_sync(0xffffffffu, s1, 2);

    float* m_sm  = (float*)(smem + SM_STATS);        // [128]
    float* rs_sm = m_sm + 128;                       // [128]
    float* g0_sm = rs_sm + 128;                      // [64]
    float* g1_sm = g0_sm + 64;                       // [64]
    const int r = wm + (lane >> 2);
    if ((lane & 3) == 0) {
        m_sm[grp * 64 + r]      = m_a;
        rs_sm[grp * 64 + r]     = s0;
        m_sm[grp * 64 + r + 8]  = m_b;
        rs_sm[grp * 64 + r + 8] = s1;
    }
    __syncthreads();
    if (tid < 64) {
        float m0v = m_sm[tid], m1v = m_sm[64 + tid];
        float r0 = rs_sm[tid], r1 = rs_sm[64 + tid];
        float REF = fmaxf(m0v, m1v);
        float f0 = __expf(m0v - REF), f1 = __expf(m1v - REF);
        float inv = 1.f / (f0 * r0 + f1 * r1);
        g0_sm[tid] = f0 * inv;
        g1_sm[tid] = f1 * inv;
    }
    __syncthreads();

    float* st1 = (float*)(smem + SM_QH);     // [64 rows][pitch 260]
    if (grp == 1) {
        float ga = g1_sm[r], gb = g1_sm[r + 8];
#pragma unroll
        for (int q = 0; q < 32; ++q) {
            int ch = q * 8 + (lane & 3) * 2;
            st1[r * 260 + ch]           = oacc[q][0] * ga;
            st1[r * 260 + ch + 1]       = oacc[q][1] * ga;
            st1[(r + 8) * 260 + ch]     = oacc[q][2] * gb;
            st1[(r + 8) * 260 + ch + 1] = oacc[q][3] * gb;
        }
    }
    __syncthreads();
    float* st2 = (float*)(smem + SM_BUF);    // [256 ch][pitch 68]
    if (grp == 0) {
        float ga = g0_sm[r], gb = g0_sm[r + 8];
#pragma unroll
        for (int q = 0; q < 32; ++q) {
            int ch = q * 8 + (lane & 3) * 2;
            st2[ch * 68 + r]           = oacc[q][0] * ga + st1[r * 260 + ch];
            st2[(ch + 1) * 68 + r]     = oacc[q][1] * ga + st1[r * 260 + ch + 1];
            st2[ch * 68 + r + 8]       = oacc[q][2] * gb + st1[(r + 8) * 260 + ch];
            st2[(ch + 1) * 68 + r + 8] = oacc[q][3] * gb + st1[(r + 8) * 260 + ch + 1];
        }
    }
    __syncthreads();
    float* outb = out + (size_t)b * Cc * Nn;
#pragma unroll
    for (int l = tid; l < 16384; l += 256) {
        int ch = l >> 6, m = l & 63;
        outb[(size_t)ch * Nn + m0 + m] = st2[ch * 68 + m];
    }
}

// ---------------------------------------------------------------------------
extern "C" void kernel_launch(void* const* d_in, const int* in_sizes, int n_in,
                              void* d_out, int out_size)
{
    (void)in_sizes; (void)n_in; (void)out_size;
    const float* x  = (const float*)d_in[0];
    const float* y  = (const float*)d_in[1];
    const float* Wq = (const float*)d_in[2];
    const float* bq = (const float*)d_in[3];
    const float* Wk = (const float*)d_in[4];
    const float* bk = (const float*)d_in[5];
    const float* Wv = (const float*)d_in[6];
    const float* bv = (const float*)d_in[7];
    float* out = (float*)d_out;

    prep_xy<<<dim3(2304, 1, 2), 256>>>((const float4*)x, (const float4*)y);
    prep_w<<<dim3(64, 1, 3), 256>>>((const float4*)Wq, (const float4*)Wk,
                                    (const float4*)Wv);
    proj_hmma<<<dim3(Nn / 64, Cc / 64, 24), 128>>>(bq, bk, bv);

    cudaFuncSetAttribute(attn_kernel,
                         cudaFuncAttributeMaxDynamicSharedMemorySize, ATTN_SMEM);
    dim3 ag(Nn / BM, Bb);
    attn_kernel<<<ag, 256, ATTN_SMEM>>>(out);
}